// round 5
// baseline (speedup 1.0000x reference)
#include <cuda_runtime.h>
#include <cuda_fp16.h>
#include <cstdint>

// ---------------- problem constants ----------------
#define INDIM 4096
#define NGRP  16
#define NOUT  256

// ---------------- device scratch ----------------
__device__ __half g_Wm[NGRP][128][256];   // folded mid weights [g][n][k]
__device__ float  g_cmid[NGRP][128];      // folded constants
__device__ __half g_Wr[NOUT][2048];       // root weights [n][k]

// ---------------- helpers ----------------
__device__ __forceinline__ unsigned smem_u32(const void* p) {
    unsigned a;
    asm("{ .reg .u64 t; cvta.to.shared.u64 t, %1; cvt.u32.u64 %0, t; }" : "=r"(a) : "l"(p));
    return a;
}
__device__ __forceinline__ void cp_async16(unsigned s, const void* g) {
    asm volatile("cp.async.cg.shared.global [%0], [%1], 16;" :: "r"(s), "l"(g));
}
#define CP_COMMIT() asm volatile("cp.async.commit_group;")
#define CP_WAIT(N)  asm volatile("cp.async.wait_group " #N ";")

__device__ __forceinline__ void ldsm4(unsigned& r0, unsigned& r1, unsigned& r2, unsigned& r3,
                                      unsigned addr) {
    asm volatile("ldmatrix.sync.aligned.m8n8.x4.shared.b16 {%0,%1,%2,%3}, [%4];"
                 : "=r"(r0), "=r"(r1), "=r"(r2), "=r"(r3) : "r"(addr));
}
__device__ __forceinline__ void mma16816(float* c, const unsigned* a, unsigned b0, unsigned b1) {
    asm volatile(
        "mma.sync.aligned.m16n8k16.row.col.f32.f16.f16.f32 "
        "{%0,%1,%2,%3},{%4,%5,%6,%7},{%8,%9},{%0,%1,%2,%3};"
        : "+f"(c[0]), "+f"(c[1]), "+f"(c[2]), "+f"(c[3])
        : "r"(a[0]), "r"(a[1]), "r"(a[2]), "r"(a[3]), "r"(b0), "r"(b1));
}
__device__ __forceinline__ float fast_tanh(float v) {
    v = fminf(fmaxf(v, -15.f), 15.f);
    float e = __expf(2.f * v);
    return __fdividef(e - 1.f, e + 1.f);
}
__device__ __forceinline__ unsigned packf2(float lo, float hi) {
    __half2 h = __floats2half2_rn(lo, hi);
    return *(unsigned*)&h;
}

// ---------------- prep (single kernel: both weight folds) ----------------
__global__ void k_prep(const float* __restrict__ w_inp, const float* __restrict__ pbias,
                       const float* __restrict__ W_mid, const float* __restrict__ b_mid,
                       const float* __restrict__ W_root) {
    if (blockIdx.x < 256) {
        // mid fold: one warp per (g, n)
        int w = (blockIdx.x * 256 + threadIdx.x) >> 5;
        int lane = threadIdx.x & 31;
        int g = w >> 7, n = w & 127;
        float sum = 0.f;
#pragma unroll
        for (int l = 0; l < 8; l++) {
            int j = l * 32 + lane;
            float wm = W_mid[(g * 256 + j) * 128 + n];
            g_Wm[g][n][j] = __float2half_rn(w_inp[g * 256 + j] * wm);
            sum += pbias[(g * 256 + j) >> 6] * wm;
        }
#pragma unroll
        for (int o = 16; o > 0; o >>= 1) sum += __shfl_xor_sync(0xffffffffu, sum, o);
        if (lane == 0) g_cmid[g][n] = sum + b_mid[g * 128 + n];
    } else {
        // root transpose+convert
        int idx = (blockIdx.x - 256) * 256 + threadIdx.x;
        int k = idx >> 8, n = idx & 255;
        g_Wr[n][k] = __float2half_rn(W_root[idx]);
    }
}

// ================= FUSED: 64 batch rows per CTA, 512 threads, flat group pipeline ========
// smem layout (bytes):
//   XH  @ 0      : [64][264]  f16 = 33792   x group tile (fp16, full K=256)
//   WM  @ 33792  : [128][264] f16 = 67584   Wm group tile (full K=256)
//   PB  @ 101376 : [64][136]  f16 = 17408   mid activations
//   WRB @ 118784 : [256][136] f16 = 69632   root weight slice
#define XHo    0u
#define WMo    33792u
#define PBo    101376u
#define WRBo   118784u
#define SMEM_TOTAL 188416
#define XSTR 264
#define PSTR 136

__device__ __forceinline__ void issue_wm(unsigned sb, int g, int tid) {
#pragma unroll
    for (int j = 0; j < 8; j++) {
        int idx = tid + j * 512;
        int n = idx >> 5, c = idx & 31;          // 32 x 16B per row of 256 halfs
        cp_async16(sb + WMo + (unsigned)(n * XSTR + c * 8) * 2u, &g_Wm[g][n][c * 8]);
    }
    CP_COMMIT();
}
__device__ __forceinline__ void issue_wr(unsigned sb, int g, int tid) {
#pragma unroll
    for (int j = 0; j < 8; j++) {
        int idx = tid + j * 512;
        int n = idx >> 4, c = idx & 15;          // 16 x 16B per row of 128 halfs
        cp_async16(sb + WRBo + (unsigned)(n * PSTR + c * 8) * 2u, &g_Wr[n][g * 128 + c * 8]);
    }
    CP_COMMIT();
}

__global__ void __launch_bounds__(512, 1) k_fused(const float* __restrict__ x,
                                                  float* __restrict__ out,
                                                  const float* __restrict__ b_root) {
    extern __shared__ char smem[];
    unsigned sb = smem_u32(smem);
    const int tid = threadIdx.x, lane = tid & 31, wid = tid >> 5;
    const int wm = wid & 1, wn = wid >> 1;        // 2 M-warps x 8 N-warps
    const long long b0 = (long long)blockIdx.x * 64;

    // x LDG mapping: thread owns row r = tid>>3, 32 consecutive k at colbase
    const int xrow = tid >> 3, xcol = (tid & 7) * 32;
    const float* xbase = x + (b0 + xrow) * INDIM + xcol;

    float racc[2][4][4];                          // root acc: 64x256/512 = 32 regs
#pragma unroll
    for (int i = 0; i < 2; i++)
#pragma unroll
        for (int j = 0; j < 4; j++)
#pragma unroll
            for (int q = 0; q < 4; q++) racc[i][j][q] = 0.f;

    // prologue: x(0) regs, Wm(0), WR(0)
    float4 xr[8];
#pragma unroll
    for (int i = 0; i < 8; i++) xr[i] = *(const float4*)(xbase + i * 4);
    issue_wm(sb, 0, tid);
    issue_wr(sb, 0, tid);

    for (int g = 0; g < NGRP; g++) {
        // stage x -> XH (fp16), then prefetch next group's x into regs
        unsigned xh_t = sb + XHo + (unsigned)(xrow * XSTR + xcol) * 2u;
#pragma unroll
        for (int i = 0; i < 4; i++) {
            uint4 v;
            v.x = packf2(xr[2 * i].x, xr[2 * i].y);
            v.y = packf2(xr[2 * i].z, xr[2 * i].w);
            v.z = packf2(xr[2 * i + 1].x, xr[2 * i + 1].y);
            v.w = packf2(xr[2 * i + 1].z, xr[2 * i + 1].w);
            *(uint4*)(smem + XHo + (unsigned)(xrow * XSTR + xcol + i * 8) * 2u) = v;
        }
        (void)xh_t;
        if (g < NGRP - 1) {
            const float* xn = xbase + (g + 1) * 256;
#pragma unroll
            for (int i = 0; i < 8; i++) xr[i] = *(const float4*)(xn + i * 4);
        }
        CP_WAIT(1);               // Wm(g) complete (WR(g) may still be in flight)
        __syncthreads();          // XH + WM visible

        // ---- mid MMA: macc = XH[64,256] @ WM[128,256]^T ----
        float macc[2][2][4];
#pragma unroll
        for (int i = 0; i < 2; i++)
#pragma unroll
            for (int j = 0; j < 2; j++)
#pragma unroll
                for (int q = 0; q < 4; q++) macc[i][j][q] = 0.f;

        unsigned Xh = sb + XHo, Wm = sb + WMo;
#pragma unroll
        for (int ks = 0; ks < 16; ks++) {
            int k0 = ks * 16;
            int grp = lane >> 3, r = lane & 7;
            int nb = wn * 16 + ((grp >> 1) << 3) + r;
            int kk = k0 + ((grp & 1) << 3);
            unsigned bfr[2][2];
            {
                unsigned q0, q1, q2, q3;
                ldsm4(q0, q1, q2, q3, Wm + (unsigned)(nb * XSTR + kk) * 2u);
                bfr[0][0] = q0; bfr[0][1] = q1;
                bfr[1][0] = q2; bfr[1][1] = q3;
            }
            int arow = wm * 32 + (lane & 15);
            int acol = k0 + ((lane >> 4) << 3);
            unsigned afr[2][4];
#pragma unroll
            for (int mt = 0; mt < 2; mt++)
                ldsm4(afr[mt][0], afr[mt][1], afr[mt][2], afr[mt][3],
                      Xh + (unsigned)((arow + mt * 16) * XSTR + acol) * 2u);
#pragma unroll
            for (int mt = 0; mt < 2; mt++)
#pragma unroll
                for (int nt = 0; nt < 2; nt++)
                    mma16816(macc[mt][nt], afr[mt], bfr[nt][0], bfr[nt][1]);
        }
        __syncthreads();                           // WM buffer free
        if (g < NGRP - 1) issue_wm(sb, g + 1, tid);  // overlaps tanh + root

        // ---- tanh -> PB (fp16) ----
#pragma unroll
        for (int mt = 0; mt < 2; mt++)
#pragma unroll
            for (int nt = 0; nt < 2; nt++) {
                int bl = wm * 32 + mt * 16 + (lane >> 2);
                int n = wn * 16 + nt * 8 + ((lane & 3) << 1);
                float2 gc = *(const float2*)&g_cmid[g][n];
                *(__half2*)(smem + PBo + (unsigned)(bl * PSTR + n) * 2u) =
                    __floats2half2_rn(fast_tanh(macc[mt][nt][0] + gc.x),
                                      fast_tanh(macc[mt][nt][1] + gc.y));
                *(__half2*)(smem + PBo + (unsigned)((bl + 8) * PSTR + n) * 2u) =
                    __floats2half2_rn(fast_tanh(macc[mt][nt][2] + gc.x),
                                      fast_tanh(macc[mt][nt][3] + gc.y));
            }
        if (g < NGRP - 1) { CP_WAIT(1); }          // WR(g) done (Wm(g+1) in flight)
        else              { CP_WAIT(0); }          // last group: drain all
        __syncthreads();                           // PB + WRB visible

        // ---- root MMA: racc += PB[64,128] @ WRB[256,128]^T ----
        unsigned Pb = sb + PBo, Wr = sb + WRBo;
#pragma unroll
        for (int ks = 0; ks < 8; ks++) {
            int k0 = ks * 16;
            unsigned bfr[4][2];
#pragma unroll
            for (int p = 0; p < 2; p++) {
                int grp = lane >> 3, r = lane & 7;
                int n = wn * 32 + p * 16 + ((grp >> 1) << 3) + r;
                int kk = k0 + ((grp & 1) << 3);
                unsigned q0, q1, q2, q3;
                ldsm4(q0, q1, q2, q3, Wr + (unsigned)(n * PSTR + kk) * 2u);
                bfr[2 * p][0] = q0; bfr[2 * p][1] = q1;
                bfr[2 * p + 1][0] = q2; bfr[2 * p + 1][1] = q3;
            }
            int arow = wm * 32 + (lane & 15);
            int acol = k0 + ((lane >> 4) << 3);
            unsigned afr[2][4];
#pragma unroll
            for (int mt = 0; mt < 2; mt++)
                ldsm4(afr[mt][0], afr[mt][1], afr[mt][2], afr[mt][3],
                      Pb + (unsigned)((arow + mt * 16) * PSTR + acol) * 2u);
#pragma unroll
            for (int mt = 0; mt < 2; mt++)
#pragma unroll
                for (int nt = 0; nt < 4; nt++)
                    mma16816(racc[mt][nt], afr[mt], bfr[nt][0], bfr[nt][1]);
        }
        __syncthreads();                           // WRB/PB/XH free for next group
        if (g < NGRP - 1) issue_wr(sb, g + 1, tid);  // overlaps next mid phase
    }

    // epilogue: smem transpose, add b_root, coalesced float4 stores
    float* trans = (float*)smem;                   // [64][260] f32
#pragma unroll
    for (int mt = 0; mt < 2; mt++)
#pragma unroll
        for (int nt = 0; nt < 4; nt++) {
            int bl = wm * 32 + mt * 16 + (lane >> 2);
            int n = wn * 32 + nt * 8 + ((lane & 3) << 1);
            *(float2*)&trans[bl * 260 + n] = make_float2(racc[mt][nt][0], racc[mt][nt][1]);
            *(float2*)&trans[(bl + 8) * 260 + n] = make_float2(racc[mt][nt][2], racc[mt][nt][3]);
        }
    __syncthreads();
#pragma unroll
    for (int j = 0; j < 8; j++) {
        int f4 = tid + j * 512;
        int b = f4 >> 6, n4 = f4 & 63;
        float4 v = *(float4*)&trans[b * 260 + n4 * 4];
        float4 br = *(const float4*)&b_root[n4 * 4];
        v.x += br.x; v.y += br.y; v.z += br.z; v.w += br.w;
        *(float4*)&out[(b0 + b) * NOUT + n4 * 4] = v;
    }
}

// ---------------- launch ----------------
extern "C" void kernel_launch(void* const* d_in, const int* in_sizes, int n_in,
                              void* d_out, int out_size) {
    const float* x      = (const float*)d_in[0];
    const float* w_inp  = (const float*)d_in[1];
    const float* pbias  = (const float*)d_in[2];
    const float* W_mid  = (const float*)d_in[3];
    const float* b_mid  = (const float*)d_in[4];
    const float* W_root = (const float*)d_in[5];
    const float* b_root = (const float*)d_in[6];
    float* out = (float*)d_out;

    int batch = in_sizes[0] / INDIM;   // 16384
    int tiles = batch / 64;            // 256 CTAs

    cudaFuncSetAttribute(k_fused, cudaFuncAttributeMaxDynamicSharedMemorySize, SMEM_TOTAL);

    k_prep<<<2304, 256>>>(w_inp, pbias, W_mid, b_mid, W_root);
    k_fused<<<tiles, 512, SMEM_TOTAL>>>(x, out, b_root);
}

// round 6
// speedup vs baseline: 1.4145x; 1.4145x over previous
#include <cuda_runtime.h>
#include <cuda_fp16.h>
#include <cstdint>

// ---------------- problem constants ----------------
#define INDIM 4096
#define NGRP  16
#define NOUT  256

// ---------------- device scratch ----------------
__device__ __half g_Wm[NGRP][128][256];   // folded mid weights [g][n][k]
__device__ float  g_cmid[NGRP][128];      // folded constants
__device__ __half g_Wr[NOUT][2048];       // root weights [n][k]
__device__ __half g_midh[16384][2048];    // mid activations fp16 [b][k]

// ---------------- helpers ----------------
__device__ __forceinline__ unsigned smem_u32(const void* p) {
    unsigned a;
    asm("{ .reg .u64 t; cvta.to.shared.u64 t, %1; cvt.u32.u64 %0, t; }" : "=r"(a) : "l"(p));
    return a;
}
__device__ __forceinline__ void cp_async16(unsigned s, const void* g) {
    asm volatile("cp.async.cg.shared.global [%0], [%1], 16;" :: "r"(s), "l"(g));
}
#define CP_COMMIT() asm volatile("cp.async.commit_group;")
#define CP_WAIT(N)  asm volatile("cp.async.wait_group " #N ";")

__device__ __forceinline__ void ldsm4(unsigned& r0, unsigned& r1, unsigned& r2, unsigned& r3,
                                      unsigned addr) {
    asm volatile("ldmatrix.sync.aligned.m8n8.x4.shared.b16 {%0,%1,%2,%3}, [%4];"
                 : "=r"(r0), "=r"(r1), "=r"(r2), "=r"(r3) : "r"(addr));
}
__device__ __forceinline__ void mma16816(float* c, const unsigned* a, unsigned b0, unsigned b1) {
    asm volatile(
        "mma.sync.aligned.m16n8k16.row.col.f32.f16.f16.f32 "
        "{%0,%1,%2,%3},{%4,%5,%6,%7},{%8,%9},{%0,%1,%2,%3};"
        : "+f"(c[0]), "+f"(c[1]), "+f"(c[2]), "+f"(c[3])
        : "r"(a[0]), "r"(a[1]), "r"(a[2]), "r"(a[3]), "r"(b0), "r"(b1));
}
__device__ __forceinline__ float fast_tanh(float v) {
    v = fminf(fmaxf(v, -15.f), 15.f);
    float e = __expf(2.f * v);
    return __fdividef(e - 1.f, e + 1.f);
}
__device__ __forceinline__ unsigned packf2(float lo, float hi) {
    __half2 h = __floats2half2_rn(lo, hi);
    return *(unsigned*)&h;
}

// ---------------- prep (single kernel) ----------------
__global__ void k_prep(const float* __restrict__ w_inp, const float* __restrict__ pbias,
                       const float* __restrict__ W_mid, const float* __restrict__ b_mid,
                       const float* __restrict__ W_root) {
    if (blockIdx.x < 256) {
        int w = (blockIdx.x * 256 + threadIdx.x) >> 5;
        int lane = threadIdx.x & 31;
        int g = w >> 7, n = w & 127;
        float sum = 0.f;
#pragma unroll
        for (int l = 0; l < 8; l++) {
            int j = l * 32 + lane;
            float wmv = W_mid[(g * 256 + j) * 128 + n];
            g_Wm[g][n][j] = __float2half_rn(w_inp[g * 256 + j] * wmv);
            sum += pbias[(g * 256 + j) >> 6] * wmv;
        }
#pragma unroll
        for (int o = 16; o > 0; o >>= 1) sum += __shfl_xor_sync(0xffffffffu, sum, o);
        if (lane == 0) g_cmid[g][n] = sum + b_mid[g * 128 + n];
    } else {
        int idx = (blockIdx.x - 256) * 256 + threadIdx.x;
        int k = idx >> 8, n = idx & 255;
        g_Wr[n][k] = __float2half_rn(W_root[idx]);
    }
}

// ================= MID GEMM: 64 rows x 128 n x K=256, one group per CTA ==============
// 256 threads, 8 warps: Mw=2 (32 rows each), Nw=4 (32 n each). 2 CTAs/SM.
// smem: 3 buffers x { XH [64][72] f16 (9216 B) + WM [128][72] f16 (18432 B) } = 82944 B
#define MSTR     72
#define MB_WM    9216u
#define MB_PAIR  27648u
#define MID_SMEM 82944

__device__ __forceinline__ void mid_issue_wm(unsigned sb, int g, int c, int buf, int tid) {
    unsigned w = sb + (unsigned)buf * MB_PAIR + MB_WM;
#pragma unroll
    for (int j = 0; j < 4; j++) {
        int idx = tid + j * 256;
        int n = idx >> 3, s = idx & 7;
        cp_async16(w + (unsigned)(n * MSTR + s * 8) * 2u, &g_Wm[g][n][c * 64 + s * 8]);
    }
    CP_COMMIT();
}

__global__ void __launch_bounds__(256, 2) k_mid(const float* __restrict__ x) {
    extern __shared__ char smem[];
    unsigned sb = smem_u32(smem);
    const int tid = threadIdx.x, lane = tid & 31, wid = tid >> 5;
    const int wmi = wid & 1, wni = wid >> 1;      // 2 M-warps x 4 N-warps
    const long long b0 = (long long)blockIdx.x * 64;
    const int g = blockIdx.y;

    // x LDG mapping: thread owns row tid>>2, 16 consecutive k at (tid&3)*16
    const int xr = tid >> 2, xc = (tid & 3) * 16;
    const float* xp = x + (b0 + xr) * INDIM + g * 256 + xc;

    float macc[2][4][4];
#pragma unroll
    for (int i = 0; i < 2; i++)
#pragma unroll
        for (int j = 0; j < 4; j++)
#pragma unroll
            for (int q = 0; q < 4; q++) macc[i][j][q] = 0.f;

    // prologue: x(0) into regs; Wm chunks 0,1 in flight
    float4 xv[4];
#pragma unroll
    for (int i = 0; i < 4; i++) xv[i] = *(const float4*)(xp + i * 4);
    mid_issue_wm(sb, g, 0, 0, tid);
    mid_issue_wm(sb, g, 1, 1, tid);

#pragma unroll
    for (int c = 0; c < 4; c++) {
        const int buf = c % 3;
        // STS x chunk c (fp16) into XH[buf]
        unsigned xh = sb + (unsigned)buf * MB_PAIR + (unsigned)(xr * MSTR + xc) * 2u;
        uint4 v0, v1;
        v0.x = packf2(xv[0].x, xv[0].y); v0.y = packf2(xv[0].z, xv[0].w);
        v0.z = packf2(xv[1].x, xv[1].y); v0.w = packf2(xv[1].z, xv[1].w);
        v1.x = packf2(xv[2].x, xv[2].y); v1.y = packf2(xv[2].z, xv[2].w);
        v1.z = packf2(xv[3].x, xv[3].y); v1.w = packf2(xv[3].z, xv[3].w);
        asm volatile("st.shared.v4.b32 [%0], {%1,%2,%3,%4};"
                     :: "r"(xh), "r"(v0.x), "r"(v0.y), "r"(v0.z), "r"(v0.w));
        asm volatile("st.shared.v4.b32 [%0], {%1,%2,%3,%4};"
                     :: "r"(xh + 16u), "r"(v1.x), "r"(v1.y), "r"(v1.z), "r"(v1.w));
        if (c < 3) {
            const float* xn = xp + (c + 1) * 64;
#pragma unroll
            for (int i = 0; i < 4; i++) xv[i] = *(const float4*)(xn + i * 4);
        }
        if (c < 3) { CP_WAIT(1); } else { CP_WAIT(0); }
        __syncthreads();
        if (c < 2) mid_issue_wm(sb, g, c + 2, (c + 2) % 3, tid);

        // MMA: macc += XH[64,64] @ WM[128,64]^T (this warp's 32x32 slice)
        unsigned Xh = sb + (unsigned)buf * MB_PAIR;
        unsigned Wb = Xh + MB_WM;
#pragma unroll
        for (int ks = 0; ks < 4; ks++) {
            int k0 = ks * 16;
            int grp = lane >> 3, r2 = lane & 7;
            int kk = k0 + ((grp & 1) << 3);
            unsigned bfr[4][2];
#pragma unroll
            for (int p = 0; p < 2; p++) {
                int nb = wni * 32 + p * 16 + ((grp >> 1) << 3) + r2;
                unsigned q0, q1, q2, q3;
                ldsm4(q0, q1, q2, q3, Wb + (unsigned)(nb * MSTR + kk) * 2u);
                bfr[2 * p][0] = q0; bfr[2 * p][1] = q1;
                bfr[2 * p + 1][0] = q2; bfr[2 * p + 1][1] = q3;
            }
            int arow = wmi * 32 + (lane & 15);
            int acol = k0 + ((lane >> 4) << 3);
            unsigned afr[2][4];
#pragma unroll
            for (int mt = 0; mt < 2; mt++)
                ldsm4(afr[mt][0], afr[mt][1], afr[mt][2], afr[mt][3],
                      Xh + (unsigned)((arow + mt * 16) * MSTR + acol) * 2u);
#pragma unroll
            for (int mt = 0; mt < 2; mt++)
#pragma unroll
                for (int nt = 0; nt < 4; nt++)
                    mma16816(macc[mt][nt], afr[mt], bfr[nt][0], bfr[nt][1]);
        }
    }

    // epilogue: tanh+c -> smem transpose tile [64][136] halfs -> coalesced uint4 stores
    __syncthreads();
#pragma unroll
    for (int mt = 0; mt < 2; mt++)
#pragma unroll
        for (int nt = 0; nt < 4; nt++) {
            int bl = wmi * 32 + mt * 16 + (lane >> 2);
            int n = wni * 32 + nt * 8 + ((lane & 3) << 1);
            float2 gc = *(const float2*)&g_cmid[g][n];
            *(__half2*)(smem + (unsigned)(bl * 136 + n) * 2u) =
                __floats2half2_rn(fast_tanh(macc[mt][nt][0] + gc.x),
                                  fast_tanh(macc[mt][nt][1] + gc.y));
            *(__half2*)(smem + (unsigned)((bl + 8) * 136 + n) * 2u) =
                __floats2half2_rn(fast_tanh(macc[mt][nt][2] + gc.x),
                                  fast_tanh(macc[mt][nt][3] + gc.y));
        }
    __syncthreads();
#pragma unroll
    for (int j = 0; j < 4; j++) {
        int idx = tid + j * 256;           // 1024 uint4 over [64][128] halfs
        int b = idx >> 4, s = idx & 15;
        uint4 v = *(uint4*)(smem + (unsigned)(b * 136 + s * 8) * 2u);
        *(uint4*)&g_midh[b0 + b][g * 128 + s * 8] = v;
    }
}

// ================= ROOT GEMM: 64 rows x 256 n x K=2048 =================
// 512 threads, 16 warps: Mw=2 (32 rows), Nw=8 (32 n). 4-deep pipeline, 1 CTA/SM.
// smem: 4 buffers x { A [64][72] f16 (9216) + B [256][72] f16 (36864) } = 184320 B
#define RSTR     72
#define RB_B     9216u
#define RB_PAIR  46080u
#define RT_SMEM  184320

__device__ __forceinline__ void root_issue(unsigned sb, long long b0, int c, int buf, int tid) {
    unsigned A = sb + (unsigned)buf * RB_PAIR, B = A + RB_B;
    {
        int r = tid >> 3, s = tid & 7;
        cp_async16(A + (unsigned)(r * RSTR + s * 8) * 2u, &g_midh[b0 + r][c * 64 + s * 8]);
    }
#pragma unroll
    for (int j = 0; j < 4; j++) {
        int idx = tid + j * 512;
        int n = idx >> 3, s = idx & 7;
        cp_async16(B + (unsigned)(n * RSTR + s * 8) * 2u, &g_Wr[n][c * 64 + s * 8]);
    }
    CP_COMMIT();
}

__global__ void __launch_bounds__(512, 1) k_root(float* __restrict__ out,
                                                 const float* __restrict__ b_root) {
    extern __shared__ char smem[];
    unsigned sb = smem_u32(smem);
    const int tid = threadIdx.x, lane = tid & 31, wid = tid >> 5;
    const int wmi = wid & 1, wni = wid >> 1;      // 2 M-warps x 8 N-warps
    const long long b0 = (long long)blockIdx.x * 64;

    float racc[2][4][4];
#pragma unroll
    for (int i = 0; i < 2; i++)
#pragma unroll
        for (int j = 0; j < 4; j++)
#pragma unroll
            for (int q = 0; q < 4; q++) racc[i][j][q] = 0.f;

    root_issue(sb, b0, 0, 0, tid);
    root_issue(sb, b0, 1, 1, tid);
    root_issue(sb, b0, 2, 2, tid);

    for (int c = 0; c < 32; c++) {
        if (c < 30)      { CP_WAIT(2); }
        else if (c == 30){ CP_WAIT(1); }
        else             { CP_WAIT(0); }
        __syncthreads();
        if (c < 29) root_issue(sb, b0, c + 3, (c + 3) & 3, tid);

        unsigned Ab = sb + (unsigned)(c & 3) * RB_PAIR;
        unsigned Bb = Ab + RB_B;
#pragma unroll
        for (int ks = 0; ks < 4; ks++) {
            int k0 = ks * 16;
            int grp = lane >> 3, r2 = lane & 7;
            int kk = k0 + ((grp & 1) << 3);
            unsigned bfr[4][2];
#pragma unroll
            for (int p = 0; p < 2; p++) {
                int nb = wni * 32 + p * 16 + ((grp >> 1) << 3) + r2;
                unsigned q0, q1, q2, q3;
                ldsm4(q0, q1, q2, q3, Bb + (unsigned)(nb * RSTR + kk) * 2u);
                bfr[2 * p][0] = q0; bfr[2 * p][1] = q1;
                bfr[2 * p + 1][0] = q2; bfr[2 * p + 1][1] = q3;
            }
            int arow = wmi * 32 + (lane & 15);
            int acol = k0 + ((lane >> 4) << 3);
            unsigned afr[2][4];
#pragma unroll
            for (int mt = 0; mt < 2; mt++)
                ldsm4(afr[mt][0], afr[mt][1], afr[mt][2], afr[mt][3],
                      Ab + (unsigned)((arow + mt * 16) * RSTR + acol) * 2u);
#pragma unroll
            for (int mt = 0; mt < 2; mt++)
#pragma unroll
                for (int nt = 0; nt < 4; nt++)
                    mma16816(racc[mt][nt], afr[mt], bfr[nt][0], bfr[nt][1]);
        }
    }

    // epilogue: + b_root, direct float2 stores (lane-quads cover 32B sectors)
#pragma unroll
    for (int mt = 0; mt < 2; mt++)
#pragma unroll
        for (int nt = 0; nt < 4; nt++) {
            int row = wmi * 32 + mt * 16 + (lane >> 2);
            int n = wni * 32 + nt * 8 + ((lane & 3) << 1);
            float2 br = *(const float2*)&b_root[n];
            *(float2*)&out[(b0 + row) * NOUT + n] =
                make_float2(racc[mt][nt][0] + br.x, racc[mt][nt][1] + br.y);
            *(float2*)&out[(b0 + row + 8) * NOUT + n] =
                make_float2(racc[mt][nt][2] + br.x, racc[mt][nt][3] + br.y);
        }
}

// ---------------- launch ----------------
extern "C" void kernel_launch(void* const* d_in, const int* in_sizes, int n_in,
                              void* d_out, int out_size) {
    const float* x      = (const float*)d_in[0];
    const float* w_inp  = (const float*)d_in[1];
    const float* pbias  = (const float*)d_in[2];
    const float* W_mid  = (const float*)d_in[3];
    const float* b_mid  = (const float*)d_in[4];
    const float* W_root = (const float*)d_in[5];
    const float* b_root = (const float*)d_in[6];
    float* out = (float*)d_out;

    int batch = in_sizes[0] / INDIM;   // 16384
    int btiles = batch / 64;           // 256

    cudaFuncSetAttribute(k_mid,  cudaFuncAttributeMaxDynamicSharedMemorySize, MID_SMEM);
    cudaFuncSetAttribute(k_root, cudaFuncAttributeMaxDynamicSharedMemorySize, RT_SMEM);

    k_prep<<<2304, 256>>>(w_inp, pbias, W_mid, b_mid, W_root);
    k_mid<<<dim3(btiles, NGRP), 256, MID_SMEM>>>(x);
    k_root<<<btiles, 512, RT_SMEM>>>(out, b_root);
}

// round 7
// speedup vs baseline: 1.5696x; 1.1096x over previous
#include <cuda_runtime.h>
#include <cuda_fp16.h>
#include <cstdint>

// ---------------- problem constants ----------------
#define INDIM 4096
#define NGRP  16
#define NOUT  256

// ---------------- device scratch ----------------
__device__ __half g_Wm[NGRP][128][256];     // folded mid weights [g][n][k] (row-major, ldsm path)
__device__ float  g_cmid[NGRP][128];        // folded constants
__device__ uint2  g_WrF[32][128][32];       // root B frags: [n8][k16][lane] -> (b0,b1)
__device__ uint4  g_midP[1024][128][32];    // root A frags: [b16][k16][lane] -> (a0..a3)

// ---------------- helpers ----------------
__device__ __forceinline__ unsigned smem_u32(const void* p) {
    unsigned a;
    asm("{ .reg .u64 t; cvta.to.shared.u64 t, %1; cvt.u32.u64 %0, t; }" : "=r"(a) : "l"(p));
    return a;
}
__device__ __forceinline__ void cp_async16(unsigned s, const void* g) {
    asm volatile("cp.async.cg.shared.global [%0], [%1], 16;" :: "r"(s), "l"(g));
}
#define CP_COMMIT() asm volatile("cp.async.commit_group;")
#define CP_WAIT(N)  asm volatile("cp.async.wait_group " #N ";")

__device__ __forceinline__ void ldsm4(unsigned& r0, unsigned& r1, unsigned& r2, unsigned& r3,
                                      unsigned addr) {
    asm volatile("ldmatrix.sync.aligned.m8n8.x4.shared.b16 {%0,%1,%2,%3}, [%4];"
                 : "=r"(r0), "=r"(r1), "=r"(r2), "=r"(r3) : "r"(addr));
}
__device__ __forceinline__ void mma16816(float* c, const unsigned* a, unsigned b0, unsigned b1) {
    asm volatile(
        "mma.sync.aligned.m16n8k16.row.col.f32.f16.f16.f32 "
        "{%0,%1,%2,%3},{%4,%5,%6,%7},{%8,%9},{%0,%1,%2,%3};"
        : "+f"(c[0]), "+f"(c[1]), "+f"(c[2]), "+f"(c[3])
        : "r"(a[0]), "r"(a[1]), "r"(a[2]), "r"(a[3]), "r"(b0), "r"(b1));
}
__device__ __forceinline__ float fast_tanh(float v) {
    v = fminf(fmaxf(v, -15.f), 15.f);
    float e = __expf(2.f * v);
    return __fdividef(e - 1.f, e + 1.f);
}
__device__ __forceinline__ unsigned packf2(float lo, float hi) {
    __half2 h = __floats2half2_rn(lo, hi);
    return *(unsigned*)&h;
}

// ---------------- prep ----------------
// blocks [0,256): fold mid weights (row-major) + constants
// blocks [256,288): build W_root B-frag layout via smem transpose (64-k slab per block)
__global__ void k_prep(const float* __restrict__ w_inp, const float* __restrict__ pbias,
                       const float* __restrict__ W_mid, const float* __restrict__ b_mid,
                       const float* __restrict__ W_root) {
    extern __shared__ float sm[];
    int tid = threadIdx.x;
    if (blockIdx.x < 256) {
        int w = (blockIdx.x * 256 + tid) >> 5;
        int lane = tid & 31;
        int g = w >> 7, n = w & 127;
        float sum = 0.f;
#pragma unroll
        for (int l = 0; l < 8; l++) {
            int j = l * 32 + lane;
            float wmv = W_mid[(g * 256 + j) * 128 + n];
            g_Wm[g][n][j] = __float2half_rn(w_inp[g * 256 + j] * wmv);
            sum += pbias[(g * 256 + j) >> 6] * wmv;
        }
#pragma unroll
        for (int o = 16; o > 0; o >>= 1) sum += __shfl_xor_sync(0xffffffffu, sum, o);
        if (lane == 0) g_cmid[g][n] = sum + b_mid[g * 128 + n];
    } else {
        int kb = blockIdx.x - 256;            // 0..31, k slab [kb*64, kb*64+64)
        // load W_root slab [64 k][256 n] coalesced into smem [64][257]
#pragma unroll
        for (int j = 0; j < 64; j++) {
            int flat = j * 256 + tid;
            int kl = flat >> 8, n = flat & 255;
            sm[kl * 257 + n] = W_root[(kb * 64 + kl) * 256 + n];
        }
        __syncthreads();
        int lane = tid & 31, w = tid >> 5;    // 8 warps x 16 tasks = 128 (n8, k16l) pairs
#pragma unroll
        for (int i = 0; i < 16; i++) {
            int t = w * 16 + i;
            int n8 = t & 31, k16l = t >> 5;   // k16l 0..3
            unsigned wd[2];
#pragma unroll
            for (int j = 0; j < 2; j++) {
                int kl = k16l * 16 + j * 8 + ((lane & 3) << 1);
                int n = n8 * 8 + (lane >> 2);
                wd[j] = packf2(sm[kl * 257 + n], sm[(kl + 1) * 257 + n]);
            }
            g_WrF[n8][kb * 4 + k16l][lane] = make_uint2(wd[0], wd[1]);
        }
    }
}

// ================= MID GEMM: 64 rows x 128 n x K=256 (one group per CTA) ==============
// 256 threads, 8 warps: Mw=2 x Nw=4, warp tile 32x32. 2 CTAs/SM.
#define MSTR     72
#define MB_WM    9216u
#define MB_PAIR  27648u
#define MID_SMEM 82944

__device__ __forceinline__ void mid_issue_wm(unsigned sb, int g, int c, int buf, int tid) {
    unsigned w = sb + (unsigned)buf * MB_PAIR + MB_WM;
#pragma unroll
    for (int j = 0; j < 4; j++) {
        int idx = tid + j * 256;
        int n = idx >> 3, s = idx & 7;
        cp_async16(w + (unsigned)(n * MSTR + s * 8) * 2u, &g_Wm[g][n][c * 64 + s * 8]);
    }
    CP_COMMIT();
}

__global__ void __launch_bounds__(256, 2) k_mid(const float* __restrict__ x) {
    extern __shared__ char smem[];
    unsigned sb = smem_u32(smem);
    const int tid = threadIdx.x, lane = tid & 31, wid = tid >> 5;
    const int wmi = wid & 1, wni = wid >> 1;      // 2 M-warps x 4 N-warps
    const long long b0 = (long long)blockIdx.x * 64;
    const int g = blockIdx.y;

    const int xr = tid >> 2, xc = (tid & 3) * 16;
    const float* xp = x + (b0 + xr) * INDIM + g * 256 + xc;

    float macc[2][4][4];
#pragma unroll
    for (int i = 0; i < 2; i++)
#pragma unroll
        for (int j = 0; j < 4; j++)
#pragma unroll
            for (int q = 0; q < 4; q++) macc[i][j][q] = 0.f;

    float4 xv[4];
#pragma unroll
    for (int i = 0; i < 4; i++) xv[i] = *(const float4*)(xp + i * 4);
    mid_issue_wm(sb, g, 0, 0, tid);
    mid_issue_wm(sb, g, 1, 1, tid);

#pragma unroll
    for (int c = 0; c < 4; c++) {
        const int buf = c % 3;
        unsigned xh = sb + (unsigned)buf * MB_PAIR + (unsigned)(xr * MSTR + xc) * 2u;
        uint4 v0, v1;
        v0.x = packf2(xv[0].x, xv[0].y); v0.y = packf2(xv[0].z, xv[0].w);
        v0.z = packf2(xv[1].x, xv[1].y); v0.w = packf2(xv[1].z, xv[1].w);
        v1.x = packf2(xv[2].x, xv[2].y); v1.y = packf2(xv[2].z, xv[2].w);
        v1.z = packf2(xv[3].x, xv[3].y); v1.w = packf2(xv[3].z, xv[3].w);
        asm volatile("st.shared.v4.b32 [%0], {%1,%2,%3,%4};"
                     :: "r"(xh), "r"(v0.x), "r"(v0.y), "r"(v0.z), "r"(v0.w));
        asm volatile("st.shared.v4.b32 [%0], {%1,%2,%3,%4};"
                     :: "r"(xh + 16u), "r"(v1.x), "r"(v1.y), "r"(v1.z), "r"(v1.w));
        if (c < 3) {
            const float* xn = xp + (c + 1) * 64;
#pragma unroll
            for (int i = 0; i < 4; i++) xv[i] = *(const float4*)(xn + i * 4);
        }
        if (c < 3) { CP_WAIT(1); } else { CP_WAIT(0); }
        __syncthreads();
        if (c < 2) mid_issue_wm(sb, g, c + 2, (c + 2) % 3, tid);

        unsigned Xh = sb + (unsigned)buf * MB_PAIR;
        unsigned Wb = Xh + MB_WM;
#pragma unroll
        for (int ks = 0; ks < 4; ks++) {
            int k0 = ks * 16;
            int grp = lane >> 3, r2 = lane & 7;
            int kk = k0 + ((grp & 1) << 3);
            unsigned bfr[4][2];
#pragma unroll
            for (int p = 0; p < 2; p++) {
                int nb = wni * 32 + p * 16 + ((grp >> 1) << 3) + r2;
                unsigned q0, q1, q2, q3;
                ldsm4(q0, q1, q2, q3, Wb + (unsigned)(nb * MSTR + kk) * 2u);
                bfr[2 * p][0] = q0; bfr[2 * p][1] = q1;
                bfr[2 * p + 1][0] = q2; bfr[2 * p + 1][1] = q3;
            }
            int arow = wmi * 32 + (lane & 15);
            int acol = k0 + ((lane >> 4) << 3);
            unsigned afr[2][4];
#pragma unroll
            for (int mt = 0; mt < 2; mt++)
                ldsm4(afr[mt][0], afr[mt][1], afr[mt][2], afr[mt][3],
                      Xh + (unsigned)((arow + mt * 16) * MSTR + acol) * 2u);
#pragma unroll
            for (int mt = 0; mt < 2; mt++)
#pragma unroll
                for (int nt = 0; nt < 4; nt++)
                    mma16816(macc[mt][nt], afr[mt], bfr[nt][0], bfr[nt][1]);
        }
    }

    // epilogue: tanh+c -> smem [64][136] -> gather into A-frag tiles -> STG.128
    __syncthreads();
#pragma unroll
    for (int mt = 0; mt < 2; mt++)
#pragma unroll
        for (int nt = 0; nt < 4; nt++) {
            int bl = wmi * 32 + mt * 16 + (lane >> 2);
            int n = wni * 32 + nt * 8 + ((lane & 3) << 1);
            float2 gc = *(const float2*)&g_cmid[g][n];
            *(__half2*)(smem + (unsigned)(bl * 136 + n) * 2u) =
                __floats2half2_rn(fast_tanh(macc[mt][nt][0] + gc.x),
                                  fast_tanh(macc[mt][nt][1] + gc.y));
            *(__half2*)(smem + (unsigned)((bl + 8) * 136 + n) * 2u) =
                __floats2half2_rn(fast_tanh(macc[mt][nt][2] + gc.x),
                                  fast_tanh(macc[mt][nt][3] + gc.y));
        }
    __syncthreads();
#pragma unroll
    for (int i = 0; i < 4; i++) {
        int t = wid * 4 + i;                 // 32 tiles: 4 bi x 8 ki
        int bi = t >> 3, ki = t & 7;
        unsigned wd[4];
#pragma unroll
        for (int j = 0; j < 4; j++) {
            int r = bi * 16 + ((j & 1) << 3) + (lane >> 2);
            int cc = ki * 16 + ((j >> 1) << 3) + ((lane & 3) << 1);
            asm volatile("ld.shared.b32 %0, [%1];"
                         : "=r"(wd[j]) : "r"(sb + (unsigned)(r * 136 + cc) * 2u));
        }
        g_midP[(int)(b0 >> 4) + bi][g * 8 + ki][lane] =
            make_uint4(wd[0], wd[1], wd[2], wd[3]);
    }
}

// ================= ROOT GEMM: 128 rows x 256 n x K=2048, smem-free frag-direct ==========
// 512 threads, 16 warps: Mw=2 x Nw=8, warp tile 64x32 (mt4 x nt4). grid=128 (one wave).
__global__ void __launch_bounds__(512, 1) k_root(float* __restrict__ out,
                                                 const float* __restrict__ b_root) {
    const int tid = threadIdx.x, lane = tid & 31, wid = tid >> 5;
    const int wmi = wid & 1, wni = wid >> 1;      // 2 M-warps x 8 N-warps
    const long long b0 = (long long)blockIdx.x * 128;
    const int bt = blockIdx.x * 8;                // b16 base

    float racc[4][4][4];
#pragma unroll
    for (int i = 0; i < 4; i++)
#pragma unroll
        for (int j = 0; j < 4; j++)
#pragma unroll
            for (int q = 0; q < 4; q++) racc[i][j][q] = 0.f;

    const char* Ap = (const char*)&g_midP[bt + wmi * 4][0][lane];   // + mt*65536 + ks*512
    const char* Bp = (const char*)&g_WrF[wni * 4][0][lane];         // + nt*32768 + ks*256

    uint4 Af[2][4];
    uint2 Bf[2][4];
#define LDA(BUF, KS)                                                                 \
    { _Pragma("unroll") for (int mt = 0; mt < 4; mt++)                               \
          Af[BUF][mt] = *(const uint4*)(Ap + mt * 65536 + (KS) * 512); }
#define LDB(BUF, KS)                                                                 \
    { _Pragma("unroll") for (int nt = 0; nt < 4; nt++)                               \
          Bf[BUF][nt] = *(const uint2*)(Bp + nt * 32768 + (KS) * 256); }
#define MMAS(BUF)                                                                    \
    { _Pragma("unroll") for (int mt = 0; mt < 4; mt++)                               \
          _Pragma("unroll") for (int nt = 0; nt < 4; nt++)                           \
              mma16816(racc[mt][nt], (const unsigned*)&Af[BUF][mt],                  \
                       Bf[BUF][nt].x, Bf[BUF][nt].y); }

    LDA(0, 0); LDB(0, 0);
#pragma unroll 1
    for (int ks = 0; ks < 128; ks += 2) {
        LDA(1, ks + 1); LDB(1, ks + 1);
        MMAS(0);
        if (ks + 2 < 128) { LDA(0, ks + 2); LDB(0, ks + 2); }
        MMAS(1);
    }

    // epilogue: + b_root, direct float2 stores
#pragma unroll
    for (int mt = 0; mt < 4; mt++)
#pragma unroll
        for (int nt = 0; nt < 4; nt++) {
            int row = wmi * 64 + mt * 16 + (lane >> 2);
            int n = wni * 32 + nt * 8 + ((lane & 3) << 1);
            float2 br = *(const float2*)&b_root[n];
            *(float2*)&out[(b0 + row) * NOUT + n] =
                make_float2(racc[mt][nt][0] + br.x, racc[mt][nt][1] + br.y);
            *(float2*)&out[(b0 + row + 8) * NOUT + n] =
                make_float2(racc[mt][nt][2] + br.x, racc[mt][nt][3] + br.y);
        }
}

// ---------------- launch ----------------
extern "C" void kernel_launch(void* const* d_in, const int* in_sizes, int n_in,
                              void* d_out, int out_size) {
    const float* x      = (const float*)d_in[0];
    const float* w_inp  = (const float*)d_in[1];
    const float* pbias  = (const float*)d_in[2];
    const float* W_mid  = (const float*)d_in[3];
    const float* b_mid  = (const float*)d_in[4];
    const float* W_root = (const float*)d_in[5];
    const float* b_root = (const float*)d_in[6];
    float* out = (float*)d_out;

    int batch = in_sizes[0] / INDIM;   // 16384

    const int PREP_SMEM = 64 * 257 * 4;   // 65792
    cudaFuncSetAttribute(k_prep, cudaFuncAttributeMaxDynamicSharedMemorySize, PREP_SMEM);
    cudaFuncSetAttribute(k_mid,  cudaFuncAttributeMaxDynamicSharedMemorySize, MID_SMEM);

    k_prep<<<288, 256, PREP_SMEM>>>(w_inp, pbias, W_mid, b_mid, W_root);
    k_mid<<<dim3(batch / 64, NGRP), 256, MID_SMEM>>>(x);
    k_root<<<batch / 128, 512>>>(out, b_root);
}